// round 2
// baseline (speedup 1.0000x reference)
#include <cuda_runtime.h>
#include <cuda_bf16.h>
#include <math.h>

#define N_NODES 100000
#define N_EDGES 1600000
#define T_STEPS 64
#define D 256
#define D_OUT 16
#define CHUNK 1562           // N_NODES / T_STEPS
#define NB_SCAN 98           // ceil(N_NODES / 1024)

// ---------------- scratch (device globals; no runtime allocation) ----------
__device__ __align__(16) int   g_cnt[N_NODES];
__device__ __align__(16) float g_dis[N_NODES];
__device__ __align__(16) int   g_row_ptr[N_NODES + 1];
__device__ __align__(16) int   g_cursor[N_NODES];
__device__ __align__(16) int   g_csr_src[N_EDGES];
__device__ __align__(16) float g_csr_coef[N_EDGES];
__device__ __align__(16) float g_bufA[(size_t)N_NODES * D];   // xw  (GEMM out)
__device__ __align__(16) float g_bufB[(size_t)N_NODES * D];   // h   (GCN out)
__device__ __align__(16) float g_pooled[T_STEPS * D];
__device__ __align__(16) float g_gx[T_STEPS * 3 * D];
__device__ __align__(16) int   g_blocksums[128];

// ---------------- CSR build ------------------------------------------------
__global__ void k_zero_cnt() {
    int i = blockIdx.x * blockDim.x + threadIdx.x;
    if (i < N_NODES) g_cnt[i] = 0;
}

__global__ void k_hist(const int* __restrict__ dst) {
    int e = blockIdx.x * blockDim.x + threadIdx.x;
    if (e < N_EDGES) {
        int d = dst[e];
        if (d >= 0 && d < N_NODES) atomicAdd(&g_cnt[d], 1);
    }
}

// block-level exclusive scan over 1024 elements (256 threads x 4)
__global__ void k_scan1() {
    __shared__ int sh[256];
    int b = blockIdx.x, tid = threadIdx.x;
    int base = b * 1024;
    int v[4];
#pragma unroll
    for (int i = 0; i < 4; i++) {
        int idx = base + tid * 4 + i;
        v[i] = (idx < N_NODES) ? g_cnt[idx] : 0;
    }
    int s = v[0] + v[1] + v[2] + v[3];
    sh[tid] = s;
    __syncthreads();
    for (int off = 1; off < 256; off <<= 1) {
        int x = (tid >= off) ? sh[tid - off] : 0;
        __syncthreads();
        sh[tid] += x;
        __syncthreads();
    }
    int excl = sh[tid] - s;
    if (tid == 255) g_blocksums[b] = sh[255];
    int run = excl;
#pragma unroll
    for (int i = 0; i < 4; i++) {
        int idx = base + tid * 4 + i;
        if (idx < N_NODES) g_row_ptr[idx] = run;
        run += v[i];
    }
}

__global__ void k_scan2(int nb) {  // single block, exclusive scan of block sums
    __shared__ int sh[128];
    int tid = threadIdx.x;
    int s = (tid < nb) ? g_blocksums[tid] : 0;
    sh[tid] = s;
    __syncthreads();
    for (int off = 1; off < 128; off <<= 1) {
        int x = (tid >= off) ? sh[tid - off] : 0;
        __syncthreads();
        sh[tid] += x;
        __syncthreads();
    }
    if (tid < nb) g_blocksums[tid] = sh[tid] - s;
}

__global__ void k_scan3() {
    int i = blockIdx.x * blockDim.x + threadIdx.x;
    if (i < N_NODES) {
        int v = g_row_ptr[i] + g_blocksums[i >> 10];
        g_row_ptr[i] = v;
        g_cursor[i]  = v;
        g_dis[i] = rsqrtf((float)g_cnt[i] + 1.0f);
    }
    if (i == 0) g_row_ptr[N_NODES] = N_EDGES;
}

__global__ void k_scatter(const int* __restrict__ src,
                          const int* __restrict__ dst) {
    int e = blockIdx.x * blockDim.x + threadIdx.x;
    if (e < N_EDGES) {
        int s = src[e], d = dst[e];
        if (s < 0 || s >= N_NODES || d < 0 || d >= N_NODES) return;
        int p = atomicAdd(&g_cursor[d], 1);
        g_csr_src[p]  = s;
        g_csr_coef[p] = g_dis[s] * g_dis[d];
    }
}

// ---------------- dense GEMM: C[M,256] = A[M,256] @ B[256,256] -------------
// 128x128 block tile, BK=8, 256 threads, 8x8 per thread. Output -> g_bufA.
// Aext == nullptr means "read from g_bufB" (layer 2 input).
__global__ __launch_bounds__(256)
void k_gemm(const float* __restrict__ Aext, const float* __restrict__ B, int M) {
    const int BM = 128, BK = 8, TM = 8, TN = 8;
    __shared__ float As[BK][BM];
    __shared__ float Bs[BK][128];
    const float* A = Aext ? Aext : g_bufB;
    const int K = 256, N = 256;
    int bm = blockIdx.y * BM;
    int bn = blockIdx.x * 128;
    int tid = threadIdx.x;
    int tx = tid % 16, ty = tid / 16;

    float acc[TM][TN];
#pragma unroll
    for (int i = 0; i < TM; i++)
#pragma unroll
        for (int j = 0; j < TN; j++) acc[i][j] = 0.0f;

    int a_row = tid >> 1;
    int a_col = (tid & 1) * 4;
    int b_row = tid >> 5;
    int b_col = (tid & 31) * 4;

    for (int k0 = 0; k0 < K; k0 += BK) {
        float4 av = make_float4(0.f, 0.f, 0.f, 0.f);
        int gr = bm + a_row;
        if (gr < M) av = *(const float4*)(A + (size_t)gr * K + k0 + a_col);
        As[a_col + 0][a_row] = av.x;
        As[a_col + 1][a_row] = av.y;
        As[a_col + 2][a_row] = av.z;
        As[a_col + 3][a_row] = av.w;
        *(float4*)&Bs[b_row][b_col] =
            *(const float4*)(B + (size_t)(k0 + b_row) * N + bn + b_col);
        __syncthreads();
#pragma unroll
        for (int k = 0; k < BK; k++) {
            float a[TM], bb[TN];
#pragma unroll
            for (int i = 0; i < TM; i += 4) *(float4*)&a[i]  = *(float4*)&As[k][ty * TM + i];
#pragma unroll
            for (int j = 0; j < TN; j += 4) *(float4*)&bb[j] = *(float4*)&Bs[k][tx * TN + j];
#pragma unroll
            for (int i = 0; i < TM; i++)
#pragma unroll
                for (int j = 0; j < TN; j++) acc[i][j] += a[i] * bb[j];
        }
        __syncthreads();
    }
#pragma unroll
    for (int i = 0; i < TM; i++) {
        int gr = bm + ty * TM + i;
        if (gr < M) {
#pragma unroll
            for (int j = 0; j < TN; j += 4) {
                *(float4*)(g_bufA + (size_t)gr * N + bn + tx * TN + j) =
                    make_float4(acc[i][j], acc[i][j + 1], acc[i][j + 2], acc[i][j + 3]);
            }
        }
    }
}

// ---------------- fused GCN aggregation + self-term + bias + ReLU ----------
// one block (128 threads) per dst node; gather-only, no atomics.
__global__ __launch_bounds__(128)
void k_gcn(const float* __restrict__ bias) {
    int d = blockIdx.x;
    int tid = threadIdx.x;
    int beg = g_row_ptr[d], end = g_row_ptr[d + 1];
    const float2* xw2 = (const float2*)g_bufA;
    float2 acc = make_float2(0.f, 0.f);
    int j = beg;
    for (; j + 1 < end; j += 2) {
        int s0 = g_csr_src[j], s1 = g_csr_src[j + 1];
        float c0 = g_csr_coef[j], c1 = g_csr_coef[j + 1];
        float2 v0 = xw2[(size_t)s0 * 128 + tid];
        float2 v1 = xw2[(size_t)s1 * 128 + tid];
        acc.x += c0 * v0.x + c1 * v1.x;
        acc.y += c0 * v0.y + c1 * v1.y;
    }
    if (j < end) {
        int s = g_csr_src[j];
        float c = g_csr_coef[j];
        float2 v = xw2[(size_t)s * 128 + tid];
        acc.x += c * v.x;
        acc.y += c * v.y;
    }
    float dis = g_dis[d];
    float d2 = dis * dis;
    float2 sv = xw2[(size_t)d * 128 + tid];
    acc.x += d2 * sv.x + bias[tid * 2];
    acc.y += d2 * sv.y + bias[tid * 2 + 1];
    acc.x = fmaxf(acc.x, 0.f);
    acc.y = fmaxf(acc.y, 0.f);
    ((float2*)g_bufB)[(size_t)d * 128 + tid] = acc;
}

// ---------------- segment mean pool ----------------------------------------
__global__ void k_pool() {
    int t = blockIdx.x;          // 0..63
    int f = threadIdx.x;         // 0..255
    const float* base = g_bufB + (size_t)t * CHUNK * D;
    float acc = 0.f;
    for (int i = 0; i < CHUNK; i++) acc += base[(size_t)i * D + f];
    g_pooled[t * D + f] = acc * (1.0f / (float)CHUNK);
}

// ---------------- gx = pooled @ w_ih^T + b_ih (parallel over t,j) ----------
__global__ void k_gx(const float* __restrict__ w_ih, const float* __restrict__ b_ih) {
    int idx = blockIdx.x * blockDim.x + threadIdx.x;
    if (idx >= T_STEPS * 3 * D) return;
    int t = idx / (3 * D), j = idx % (3 * D);
    const float4* w = (const float4*)(w_ih + (size_t)j * D);
    const float4* p = (const float4*)(g_pooled + t * D);
    float acc = b_ih[j];
#pragma unroll 4
    for (int k = 0; k < D / 4; k++) {
        float4 a = w[k], b = p[k];
        acc += a.x * b.x + a.y * b.y + a.z * b.z + a.w * b.w;
    }
    g_gx[idx] = acc;
}

// ---------------- sequential GRU + classifier (single block) ---------------
__global__ __launch_bounds__(768)
void k_gru(const float* __restrict__ w_hh, const float* __restrict__ b_hh,
           const float* __restrict__ Wc, const float* __restrict__ bc,
           float* __restrict__ out) {
    __shared__ float h_sh[D];
    __shared__ float gh_sh[3 * D];
    int tid = threadIdx.x;
    int warp = tid >> 5, lane = tid & 31;
    if (tid < D) h_sh[tid] = 0.f;
    __syncthreads();

    for (int t = 0; t < T_STEPS; t++) {
        // gh[r] = b_hh[r] + w_hh[r,:] . h   — warp-per-row, coalesced
#pragma unroll 4
        for (int rr = 0; rr < 32; rr++) {
            int r = warp * 32 + rr;
            const float4* w = (const float4*)(w_hh + (size_t)r * D + lane * 8);
            float4 a0 = w[0], a1 = w[1];
            float4 h0 = *(const float4*)(h_sh + lane * 8);
            float4 h1 = *(const float4*)(h_sh + lane * 8 + 4);
            float p = a0.x * h0.x + a0.y * h0.y + a0.z * h0.z + a0.w * h0.w
                    + a1.x * h1.x + a1.y * h1.y + a1.z * h1.z + a1.w * h1.w;
#pragma unroll
            for (int o = 16; o > 0; o >>= 1) p += __shfl_down_sync(0xffffffffu, p, o);
            if (lane == 0) gh_sh[r] = p + b_hh[r];
        }
        __syncthreads();
        float hnew = 0.f;
        if (tid < D) {
            float xr = g_gx[t * 3 * D + tid];
            float xz = g_gx[t * 3 * D + D + tid];
            float xn = g_gx[t * 3 * D + 2 * D + tid];
            float r_ = 1.f / (1.f + expf(-(xr + gh_sh[tid])));
            float z_ = 1.f / (1.f + expf(-(xz + gh_sh[D + tid])));
            float n_ = tanhf(xn + r_ * gh_sh[2 * D + tid]);
            hnew = (1.f - z_) * n_ + z_ * h_sh[tid];
        }
        __syncthreads();
        if (tid < D) h_sh[tid] = hnew;
        __syncthreads();
    }
    if (tid < D_OUT) {
        float acc = bc[tid];
        for (int k = 0; k < D; k++) acc += Wc[(size_t)tid * D + k] * h_sh[k];
        out[tid] = acc;
    }
}

// ---------------- launch ----------------------------------------------------
extern "C" void kernel_launch(void* const* d_in, const int* in_sizes, int n_in,
                              void* d_out, int out_size) {
    // Expected order (setup_inputs dict order):
    // 0:x 1:edge_index 2:ptr 3:W1 4:b1 5:W2 6:b2 7:w_ih 8:w_hh 9:b_ih 10:b_hh 11:Wc 12:bc
    // Defensive: locate edge_index and x by element count in case order differs.
    int idx_x = 0, idx_ei = 1;
    if (in_sizes[idx_ei] != 2 * N_EDGES) {
        for (int i = 0; i < n_in; i++) if (in_sizes[i] == 2 * N_EDGES) { idx_ei = i; break; }
    }
    if (in_sizes[idx_x] != N_NODES * D) {
        for (int i = 0; i < n_in; i++) if (in_sizes[i] == N_NODES * D) { idx_x = i; break; }
    }

    const float* x    = (const float*)d_in[idx_x];
    const int*   ei   = (const int*)d_in[idx_ei];   // int32 (JAX x64 disabled)
    const float* W1   = (const float*)d_in[3];
    const float* b1   = (const float*)d_in[4];
    const float* W2   = (const float*)d_in[5];
    const float* b2   = (const float*)d_in[6];
    const float* w_ih = (const float*)d_in[7];
    const float* w_hh = (const float*)d_in[8];
    const float* b_ih = (const float*)d_in[9];
    const float* b_hh = (const float*)d_in[10];
    const float* Wc   = (const float*)d_in[11];
    const float* bc   = (const float*)d_in[12];
    float* out = (float*)d_out;

    const int* src = ei;
    const int* dst = ei + N_EDGES;

    // CSR by dst (counting sort), deg_inv_sqrt
    k_zero_cnt<<<(N_NODES + 255) / 256, 256>>>();
    k_hist<<<(N_EDGES + 255) / 256, 256>>>(dst);
    k_scan1<<<NB_SCAN, 256>>>();
    k_scan2<<<1, 128>>>(NB_SCAN);
    k_scan3<<<(N_NODES + 255) / 256, 256>>>();
    k_scatter<<<(N_EDGES + 255) / 256, 256>>>(src, dst);

    dim3 gemmGrid(2, (N_NODES + 127) / 128);

    // layer 1: xw = x @ W1 ; h1 = relu(gcn(xw) + b1)
    k_gemm<<<gemmGrid, 256>>>(x, W1, N_NODES);
    k_gcn<<<N_NODES, 128>>>(b1);

    // layer 2: xw = h1 @ W2 ; h2 = relu(gcn(xw) + b2)
    k_gemm<<<gemmGrid, 256>>>(nullptr, W2, N_NODES);
    k_gcn<<<N_NODES, 128>>>(b2);

    // pool -> gx -> GRU -> classifier
    k_pool<<<T_STEPS, 256>>>();
    k_gx<<<(T_STEPS * 3 * D + 127) / 128, 128>>>(w_ih, b_ih);
    k_gru<<<1, 768>>>(w_hh, b_hh, Wc, bc, out);
}

// round 3
// speedup vs baseline: 1.1257x; 1.1257x over previous
#include <cuda_runtime.h>
#include <cuda_bf16.h>
#include <math.h>

#define N_NODES 100000
#define N_EDGES 1600000
#define T_STEPS 64
#define D 256
#define D_OUT 16
#define CHUNK 1562           // N_NODES / T_STEPS
#define NB_SCAN 98           // ceil(N_NODES / 1024)

// ---------------- scratch (device globals; no runtime allocation) ----------
__device__ __align__(16) int   g_cnt[N_NODES];
__device__ __align__(16) float g_dis[N_NODES];
__device__ __align__(16) int   g_row_ptr[N_NODES + 1];
__device__ __align__(16) int   g_cursor[N_NODES];
__device__ __align__(16) int   g_csr_src[N_EDGES];
__device__ __align__(16) float g_csr_coef[N_EDGES];
__device__ __align__(16) float g_bufA[(size_t)N_NODES * D];   // xw  (GEMM out)
__device__ __align__(16) float g_bufB[(size_t)N_NODES * D];   // h   (GCN out)
__device__ __align__(16) float g_pooled[T_STEPS * D];
__device__ __align__(16) float g_gx[T_STEPS * 3 * D];
__device__ __align__(16) int   g_blocksums[128];

// ---------------- CSR build ------------------------------------------------
__global__ void k_zero_cnt() {
    int i = blockIdx.x * blockDim.x + threadIdx.x;
    if (i < N_NODES) g_cnt[i] = 0;
}

__global__ void k_hist(const int* __restrict__ dst) {
    int e = blockIdx.x * blockDim.x + threadIdx.x;
    if (e < N_EDGES) {
        int d = dst[e];
        if (d >= 0 && d < N_NODES) atomicAdd(&g_cnt[d], 1);
    }
}

// block-level exclusive scan over 1024 elements (256 threads x 4)
__global__ void k_scan1() {
    __shared__ int sh[256];
    int b = blockIdx.x, tid = threadIdx.x;
    int base = b * 1024;
    int v[4];
#pragma unroll
    for (int i = 0; i < 4; i++) {
        int idx = base + tid * 4 + i;
        v[i] = (idx < N_NODES) ? g_cnt[idx] : 0;
    }
    int s = v[0] + v[1] + v[2] + v[3];
    sh[tid] = s;
    __syncthreads();
    for (int off = 1; off < 256; off <<= 1) {
        int x = (tid >= off) ? sh[tid - off] : 0;
        __syncthreads();
        sh[tid] += x;
        __syncthreads();
    }
    int excl = sh[tid] - s;
    if (tid == 255) g_blocksums[b] = sh[255];
    int run = excl;
#pragma unroll
    for (int i = 0; i < 4; i++) {
        int idx = base + tid * 4 + i;
        if (idx < N_NODES) g_row_ptr[idx] = run;
        run += v[i];
    }
}

__global__ void k_scan2(int nb) {  // single block, exclusive scan of block sums
    __shared__ int sh[128];
    int tid = threadIdx.x;
    int s = (tid < nb) ? g_blocksums[tid] : 0;
    sh[tid] = s;
    __syncthreads();
    for (int off = 1; off < 128; off <<= 1) {
        int x = (tid >= off) ? sh[tid - off] : 0;
        __syncthreads();
        sh[tid] += x;
        __syncthreads();
    }
    if (tid < nb) g_blocksums[tid] = sh[tid] - s;
}

__global__ void k_scan3() {
    int i = blockIdx.x * blockDim.x + threadIdx.x;
    if (i < N_NODES) {
        int v = g_row_ptr[i] + g_blocksums[i >> 10];
        g_row_ptr[i] = v;
        g_cursor[i]  = v;
        g_dis[i] = rsqrtf((float)g_cnt[i] + 1.0f);
    }
    if (i == 0) g_row_ptr[N_NODES] = N_EDGES;
}

__global__ void k_scatter(const int* __restrict__ src,
                          const int* __restrict__ dst) {
    int e = blockIdx.x * blockDim.x + threadIdx.x;
    if (e < N_EDGES) {
        int s = src[e], d = dst[e];
        if (s < 0 || s >= N_NODES || d < 0 || d >= N_NODES) return;
        int p = atomicAdd(&g_cursor[d], 1);
        g_csr_src[p]  = s;
        g_csr_coef[p] = g_dis[s] * g_dis[d];
    }
}

// ---------------- tensor-core GEMM (3xTF32): C = A[M,256] @ B[256,256] -----
// block tile 128(M) x 64(N), 8 warps = 4(M) x 2(N), warp tile 32x32.
// mma.sync.m16n8k8.tf32 with hi/lo split -> ~fp32 accuracy.
#define AS_PITCH 36   // bank-conflict-free A fragment loads (4r+c covers 32 banks)
#define BS_PITCH 72   // bank-conflict-free B fragment loads (8k+n covers 32 banks)

__device__ __forceinline__ unsigned f32_to_tf32(float f) {
    unsigned r;
    asm("cvt.rna.tf32.f32 %0, %1;" : "=r"(r) : "f"(f));
    return r;
}
__device__ __forceinline__ void split_tf32(float f, unsigned& hi, unsigned& lo) {
    hi = f32_to_tf32(f);
    lo = f32_to_tf32(f - __uint_as_float(hi));
}
__device__ __forceinline__ void mma_tf32(float* c, const unsigned* a, const unsigned* b) {
    asm volatile(
        "mma.sync.aligned.m16n8k8.row.col.f32.tf32.tf32.f32 "
        "{%0,%1,%2,%3}, {%4,%5,%6,%7}, {%8,%9}, {%0,%1,%2,%3};"
        : "+f"(c[0]), "+f"(c[1]), "+f"(c[2]), "+f"(c[3])
        : "r"(a[0]), "r"(a[1]), "r"(a[2]), "r"(a[3]), "r"(b[0]), "r"(b[1]));
}

__global__ __launch_bounds__(256)
void k_gemm_tc(const float* __restrict__ Aext, const float* __restrict__ B, int M) {
    __shared__ float As[128][AS_PITCH];
    __shared__ float Bs[32][BS_PITCH];
    const float* A = Aext ? Aext : g_bufB;
    const int K = 256, N = 256;

    int bm = blockIdx.y * 128;
    int bn = blockIdx.x * 64;
    int tid  = threadIdx.x;
    int warp = tid >> 5, lane = tid & 31;
    int wm = warp & 3;          // 0..3 (M)
    int wn = warp >> 2;         // 0..1 (N)
    int lq = lane >> 2;         // 0..7
    int lr = lane & 3;          // 0..3

    float acc[2][4][4];
#pragma unroll
    for (int i = 0; i < 2; i++)
#pragma unroll
        for (int j = 0; j < 4; j++)
#pragma unroll
            for (int v = 0; v < 4; v++) acc[i][j][v] = 0.f;

    for (int k0 = 0; k0 < K; k0 += 32) {
        // load A tile: 128x32 floats = 1024 float4, 4 per thread, coalesced
#pragma unroll
        for (int i = 0; i < 4; i++) {
            int f = tid + 256 * i;
            int row = f >> 3, c4 = f & 7;
            float4 v = make_float4(0.f, 0.f, 0.f, 0.f);
            int gr = bm + row;
            if (gr < M) v = *(const float4*)(A + (size_t)gr * K + k0 + c4 * 4);
            *(float4*)&As[row][c4 * 4] = v;
        }
        // load B tile: 32x64 floats = 512 float4, 2 per thread
#pragma unroll
        for (int i = 0; i < 2; i++) {
            int f = tid + 256 * i;
            int row = f >> 4, c4 = f & 15;
            *(float4*)&Bs[row][c4 * 4] =
                *(const float4*)(B + (size_t)(k0 + row) * N + bn + c4 * 4);
        }
        __syncthreads();

#pragma unroll
        for (int ks = 0; ks < 4; ks++) {
            int k = ks * 8;
            // A fragments: 2 m-tiles x 4 regs, split hi/lo
            unsigned aHi[2][4], aLo[2][4];
#pragma unroll
            for (int mt = 0; mt < 2; mt++) {
                int r0 = wm * 32 + mt * 16 + lq;
                float f0 = As[r0    ][k + lr];
                float f1 = As[r0 + 8][k + lr];
                float f2 = As[r0    ][k + 4 + lr];
                float f3 = As[r0 + 8][k + 4 + lr];
                split_tf32(f0, aHi[mt][0], aLo[mt][0]);
                split_tf32(f1, aHi[mt][1], aLo[mt][1]);
                split_tf32(f2, aHi[mt][2], aLo[mt][2]);
                split_tf32(f3, aHi[mt][3], aLo[mt][3]);
            }
            // B fragments: 4 n-tiles x 2 regs, split hi/lo
            unsigned bHi[4][2], bLo[4][2];
#pragma unroll
            for (int nt = 0; nt < 4; nt++) {
                int c = wn * 32 + nt * 8 + lq;
                float f0 = Bs[k + lr    ][c];
                float f1 = Bs[k + 4 + lr][c];
                split_tf32(f0, bHi[nt][0], bLo[nt][0]);
                split_tf32(f1, bHi[nt][1], bLo[nt][1]);
            }
            // 3xTF32 passes
#pragma unroll
            for (int mt = 0; mt < 2; mt++)
#pragma unroll
                for (int nt = 0; nt < 4; nt++) {
                    mma_tf32(acc[mt][nt], aLo[mt], bHi[nt]);
                    mma_tf32(acc[mt][nt], aHi[mt], bLo[nt]);
                    mma_tf32(acc[mt][nt], aHi[mt], bHi[nt]);
                }
        }
        __syncthreads();
    }

    // epilogue: write fp32 to g_bufA
#pragma unroll
    for (int mt = 0; mt < 2; mt++) {
#pragma unroll
        for (int nt = 0; nt < 4; nt++) {
            int gr0 = bm + wm * 32 + mt * 16 + lq;
            int gc  = bn + wn * 32 + nt * 8 + lr * 2;
            if (gr0 < M)
                *(float2*)(g_bufA + (size_t)gr0 * N + gc) =
                    make_float2(acc[mt][nt][0], acc[mt][nt][1]);
            if (gr0 + 8 < M)
                *(float2*)(g_bufA + (size_t)(gr0 + 8) * N + gc) =
                    make_float2(acc[mt][nt][2], acc[mt][nt][3]);
        }
    }
}

// ---------------- fused GCN aggregation + self-term + bias + ReLU ----------
// one block (128 threads) per dst node; gather-only, no atomics. 4-edge unroll.
__global__ __launch_bounds__(128)
void k_gcn(const float* __restrict__ bias) {
    int d = blockIdx.x;
    int tid = threadIdx.x;
    int beg = g_row_ptr[d], end = g_row_ptr[d + 1];
    const float2* xw2 = (const float2*)g_bufA;
    float2 acc = make_float2(0.f, 0.f);
    int j = beg;
    for (; j + 3 < end; j += 4) {
        int s0 = g_csr_src[j],     s1 = g_csr_src[j + 1];
        int s2 = g_csr_src[j + 2], s3 = g_csr_src[j + 3];
        float c0 = g_csr_coef[j],     c1 = g_csr_coef[j + 1];
        float c2 = g_csr_coef[j + 2], c3 = g_csr_coef[j + 3];
        float2 v0 = xw2[(size_t)s0 * 128 + tid];
        float2 v1 = xw2[(size_t)s1 * 128 + tid];
        float2 v2 = xw2[(size_t)s2 * 128 + tid];
        float2 v3 = xw2[(size_t)s3 * 128 + tid];
        acc.x += c0 * v0.x + c1 * v1.x + c2 * v2.x + c3 * v3.x;
        acc.y += c0 * v0.y + c1 * v1.y + c2 * v2.y + c3 * v3.y;
    }
    for (; j < end; j++) {
        int s = g_csr_src[j];
        float c = g_csr_coef[j];
        float2 v = xw2[(size_t)s * 128 + tid];
        acc.x += c * v.x;
        acc.y += c * v.y;
    }
    float dis = g_dis[d];
    float d2 = dis * dis;
    float2 sv = xw2[(size_t)d * 128 + tid];
    acc.x += d2 * sv.x + bias[tid * 2];
    acc.y += d2 * sv.y + bias[tid * 2 + 1];
    acc.x = fmaxf(acc.x, 0.f);
    acc.y = fmaxf(acc.y, 0.f);
    ((float2*)g_bufB)[(size_t)d * 128 + tid] = acc;
}

// ---------------- segment mean pool ----------------------------------------
__global__ void k_pool() {
    int t = blockIdx.x;          // 0..63
    int f = threadIdx.x;         // 0..255
    const float* base = g_bufB + (size_t)t * CHUNK * D;
    float acc = 0.f;
    for (int i = 0; i < CHUNK; i++) acc += base[(size_t)i * D + f];
    g_pooled[t * D + f] = acc * (1.0f / (float)CHUNK);
}

// ---------------- gx = pooled @ w_ih^T + b_ih (parallel over t,j) ----------
__global__ void k_gx(const float* __restrict__ w_ih, const float* __restrict__ b_ih) {
    int idx = blockIdx.x * blockDim.x + threadIdx.x;
    if (idx >= T_STEPS * 3 * D) return;
    int t = idx / (3 * D), j = idx % (3 * D);
    const float4* w = (const float4*)(w_ih + (size_t)j * D);
    const float4* p = (const float4*)(g_pooled + t * D);
    float acc = b_ih[j];
#pragma unroll 4
    for (int k = 0; k < D / 4; k++) {
        float4 a = w[k], b = p[k];
        acc += a.x * b.x + a.y * b.y + a.z * b.z + a.w * b.w;
    }
    g_gx[idx] = acc;
}

// ---------------- sequential GRU + classifier (single block) ---------------
__global__ __launch_bounds__(768)
void k_gru(const float* __restrict__ w_hh, const float* __restrict__ b_hh,
           const float* __restrict__ Wc, const float* __restrict__ bc,
           float* __restrict__ out) {
    __shared__ float h_sh[D];
    __shared__ float gh_sh[3 * D];
    int tid = threadIdx.x;
    int warp = tid >> 5, lane = tid & 31;
    if (tid < D) h_sh[tid] = 0.f;
    __syncthreads();

    for (int t = 0; t < T_STEPS; t++) {
        // gh[r] = b_hh[r] + w_hh[r,:] . h   — warp-per-row, coalesced
#pragma unroll 4
        for (int rr = 0; rr < 32; rr++) {
            int r = warp * 32 + rr;
            const float4* w = (const float4*)(w_hh + (size_t)r * D + lane * 8);
            float4 a0 = w[0], a1 = w[1];
            float4 h0 = *(const float4*)(h_sh + lane * 8);
            float4 h1 = *(const float4*)(h_sh + lane * 8 + 4);
            float p = a0.x * h0.x + a0.y * h0.y + a0.z * h0.z + a0.w * h0.w
                    + a1.x * h1.x + a1.y * h1.y + a1.z * h1.z + a1.w * h1.w;
#pragma unroll
            for (int o = 16; o > 0; o >>= 1) p += __shfl_down_sync(0xffffffffu, p, o);
            if (lane == 0) gh_sh[r] = p + b_hh[r];
        }
        __syncthreads();
        float hnew = 0.f;
        if (tid < D) {
            float xr = g_gx[t * 3 * D + tid];
            float xz = g_gx[t * 3 * D + D + tid];
            float xn = g_gx[t * 3 * D + 2 * D + tid];
            float r_ = 1.f / (1.f + expf(-(xr + gh_sh[tid])));
            float z_ = 1.f / (1.f + expf(-(xz + gh_sh[D + tid])));
            float n_ = tanhf(xn + r_ * gh_sh[2 * D + tid]);
            hnew = (1.f - z_) * n_ + z_ * h_sh[tid];
        }
        __syncthreads();
        if (tid < D) h_sh[tid] = hnew;
        __syncthreads();
    }
    if (tid < D_OUT) {
        float acc = bc[tid];
        for (int k = 0; k < D; k++) acc += Wc[(size_t)tid * D + k] * h_sh[k];
        out[tid] = acc;
    }
}

// ---------------- launch ----------------------------------------------------
extern "C" void kernel_launch(void* const* d_in, const int* in_sizes, int n_in,
                              void* d_out, int out_size) {
    // 0:x 1:edge_index 2:ptr 3:W1 4:b1 5:W2 6:b2 7:w_ih 8:w_hh 9:b_ih 10:b_hh 11:Wc 12:bc
    int idx_x = 0, idx_ei = 1;
    if (in_sizes[idx_ei] != 2 * N_EDGES) {
        for (int i = 0; i < n_in; i++) if (in_sizes[i] == 2 * N_EDGES) { idx_ei = i; break; }
    }
    if (in_sizes[idx_x] != N_NODES * D) {
        for (int i = 0; i < n_in; i++) if (in_sizes[i] == N_NODES * D) { idx_x = i; break; }
    }

    const float* x    = (const float*)d_in[idx_x];
    const int*   ei   = (const int*)d_in[idx_ei];   // int32 (JAX x64 disabled)
    const float* W1   = (const float*)d_in[3];
    const float* b1   = (const float*)d_in[4];
    const float* W2   = (const float*)d_in[5];
    const float* b2   = (const float*)d_in[6];
    const float* w_ih = (const float*)d_in[7];
    const float* w_hh = (const float*)d_in[8];
    const float* b_ih = (const float*)d_in[9];
    const float* b_hh = (const float*)d_in[10];
    const float* Wc   = (const float*)d_in[11];
    const float* bc   = (const float*)d_in[12];
    float* out = (float*)d_out;

    const int* src = ei;
    const int* dst = ei + N_EDGES;

    // CSR by dst (counting sort), deg_inv_sqrt
    k_zero_cnt<<<(N_NODES + 255) / 256, 256>>>();
    k_hist<<<(N_EDGES + 255) / 256, 256>>>(dst);
    k_scan1<<<NB_SCAN, 256>>>();
    k_scan2<<<1, 128>>>(NB_SCAN);
    k_scan3<<<(N_NODES + 255) / 256, 256>>>();
    k_scatter<<<(N_EDGES + 255) / 256, 256>>>(src, dst);

    dim3 gemmGrid(4, (N_NODES + 127) / 128);   // N=256 / 64 = 4

    // layer 1: xw = x @ W1 ; h1 = relu(gcn(xw) + b1)
    k_gemm_tc<<<gemmGrid, 256>>>(x, W1, N_NODES);
    k_gcn<<<N_NODES, 128>>>(b1);

    // layer 2: xw = h1 @ W2 ; h2 = relu(gcn(xw) + b2)
    k_gemm_tc<<<gemmGrid, 256>>>(nullptr, W2, N_NODES);
    k_gcn<<<N_NODES, 128>>>(b2);

    // pool -> gx -> GRU -> classifier
    k_pool<<<T_STEPS, 256>>>();
    k_gx<<<(T_STEPS * 3 * D + 127) / 128, 128>>>(w_ih, b_ih);
    k_gru<<<1, 768>>>(w_hh, b_hh, Wc, bc, out);
}

// round 4
// speedup vs baseline: 1.6531x; 1.4685x over previous
#include <cuda_runtime.h>
#include <cuda_bf16.h>
#include <math.h>

#define N_NODES 100000
#define N_EDGES 1600000
#define T_STEPS 64
#define D 256
#define D_OUT 16
#define CHUNK 1562           // N_NODES / T_STEPS
#define NB_SCAN 98           // ceil(N_NODES / 1024)
#define GRU_NB 32            // GRU blocks
#define GRU_UPB 8            // hidden units per GRU block (32*8 = 256)
#define POOL_PARTS 16

// ---------------- scratch (device globals; no runtime allocation) ----------
__device__ __align__(16) int   g_cnt[N_NODES];
__device__ __align__(16) float g_dis[N_NODES];
__device__ __align__(16) int   g_row_ptr[N_NODES + 1];
__device__ __align__(16) int   g_cursor[N_NODES];
__device__ __align__(16) int   g_csr_src[N_EDGES];
__device__ __align__(16) float g_csr_coef[N_EDGES];
__device__ __align__(16) float g_bufA[(size_t)N_NODES * D];   // xw  (GEMM out)
__device__ __align__(16) float g_bufB[(size_t)N_NODES * D];   // h   (GCN out)
__device__ __align__(16) float g_pooled[T_STEPS * D];
__device__ __align__(16) float g_ppart[T_STEPS][POOL_PARTS][D];
__device__ __align__(16) float g_gx[T_STEPS * 3 * D];
__device__ __align__(16) int   g_blocksums[128];
__device__ volatile int   g_gru_flag[T_STEPS + 2][GRU_NB];
__device__ volatile float g_h[D];

// ---------------- CSR build ------------------------------------------------
__global__ void k_zero_cnt() {
    int i = blockIdx.x * blockDim.x + threadIdx.x;
    if (i < N_NODES) g_cnt[i] = 0;
}

__global__ void k_hist(const int* __restrict__ dst) {
    int e = blockIdx.x * blockDim.x + threadIdx.x;
    if (e < N_EDGES) {
        int d = dst[e];
        if (d >= 0 && d < N_NODES) atomicAdd(&g_cnt[d], 1);
    }
}

// block-level exclusive scan over 1024 elements (256 threads x 4)
__global__ void k_scan1() {
    __shared__ int sh[256];
    int b = blockIdx.x, tid = threadIdx.x;
    int base = b * 1024;
    int v[4];
#pragma unroll
    for (int i = 0; i < 4; i++) {
        int idx = base + tid * 4 + i;
        v[i] = (idx < N_NODES) ? g_cnt[idx] : 0;
    }
    int s = v[0] + v[1] + v[2] + v[3];
    sh[tid] = s;
    __syncthreads();
    for (int off = 1; off < 256; off <<= 1) {
        int x = (tid >= off) ? sh[tid - off] : 0;
        __syncthreads();
        sh[tid] += x;
        __syncthreads();
    }
    int excl = sh[tid] - s;
    if (tid == 255) g_blocksums[b] = sh[255];
    int run = excl;
#pragma unroll
    for (int i = 0; i < 4; i++) {
        int idx = base + tid * 4 + i;
        if (idx < N_NODES) g_row_ptr[idx] = run;
        run += v[i];
    }
}

__global__ void k_scan2(int nb) {  // single block, exclusive scan of block sums
    __shared__ int sh[128];
    int tid = threadIdx.x;
    int s = (tid < nb) ? g_blocksums[tid] : 0;
    sh[tid] = s;
    __syncthreads();
    for (int off = 1; off < 128; off <<= 1) {
        int x = (tid >= off) ? sh[tid - off] : 0;
        __syncthreads();
        sh[tid] += x;
        __syncthreads();
    }
    if (tid < nb) g_blocksums[tid] = sh[tid] - s;
}

__global__ void k_scan3() {
    int i = blockIdx.x * blockDim.x + threadIdx.x;
    if (i < N_NODES) {
        int v = g_row_ptr[i] + g_blocksums[i >> 10];
        g_row_ptr[i] = v;
        g_cursor[i]  = v;
        g_dis[i] = rsqrtf((float)g_cnt[i] + 1.0f);
    }
    if (i == 0) g_row_ptr[N_NODES] = N_EDGES;
}

__global__ void k_scatter(const int* __restrict__ src,
                          const int* __restrict__ dst) {
    int e = blockIdx.x * blockDim.x + threadIdx.x;
    if (e < N_EDGES) {
        int s = src[e], d = dst[e];
        if (s < 0 || s >= N_NODES || d < 0 || d >= N_NODES) return;
        int p = atomicAdd(&g_cursor[d], 1);
        g_csr_src[p]  = s;
        g_csr_coef[p] = g_dis[s] * g_dis[d];
    }
}

// ---------------- tensor-core GEMM (3xTF32): C = A[M,256] @ B[256,256] -----
#define AS_PITCH 36
#define BS_PITCH 72

__device__ __forceinline__ unsigned f32_to_tf32(float f) {
    unsigned r;
    asm("cvt.rna.tf32.f32 %0, %1;" : "=r"(r) : "f"(f));
    return r;
}
__device__ __forceinline__ void split_tf32(float f, unsigned& hi, unsigned& lo) {
    hi = f32_to_tf32(f);
    lo = f32_to_tf32(f - __uint_as_float(hi));
}
__device__ __forceinline__ void mma_tf32(float* c, const unsigned* a, const unsigned* b) {
    asm volatile(
        "mma.sync.aligned.m16n8k8.row.col.f32.tf32.tf32.f32 "
        "{%0,%1,%2,%3}, {%4,%5,%6,%7}, {%8,%9}, {%0,%1,%2,%3};"
        : "+f"(c[0]), "+f"(c[1]), "+f"(c[2]), "+f"(c[3])
        : "r"(a[0]), "r"(a[1]), "r"(a[2]), "r"(a[3]), "r"(b[0]), "r"(b[1]));
}

__global__ __launch_bounds__(256)
void k_gemm_tc(const float* __restrict__ Aext, const float* __restrict__ B, int M) {
    __shared__ float As[128][AS_PITCH];
    __shared__ float Bs[32][BS_PITCH];
    const float* A = Aext ? Aext : g_bufB;
    const int K = 256, N = 256;

    int bm = blockIdx.y * 128;
    int bn = blockIdx.x * 64;
    int tid  = threadIdx.x;
    int warp = tid >> 5, lane = tid & 31;
    int wm = warp & 3;
    int wn = warp >> 2;
    int lq = lane >> 2;
    int lr = lane & 3;

    float acc[2][4][4];
#pragma unroll
    for (int i = 0; i < 2; i++)
#pragma unroll
        for (int j = 0; j < 4; j++)
#pragma unroll
            for (int v = 0; v < 4; v++) acc[i][j][v] = 0.f;

    for (int k0 = 0; k0 < K; k0 += 32) {
#pragma unroll
        for (int i = 0; i < 4; i++) {
            int f = tid + 256 * i;
            int row = f >> 3, c4 = f & 7;
            float4 v = make_float4(0.f, 0.f, 0.f, 0.f);
            int gr = bm + row;
            if (gr < M) v = *(const float4*)(A + (size_t)gr * K + k0 + c4 * 4);
            *(float4*)&As[row][c4 * 4] = v;
        }
#pragma unroll
        for (int i = 0; i < 2; i++) {
            int f = tid + 256 * i;
            int row = f >> 4, c4 = f & 15;
            *(float4*)&Bs[row][c4 * 4] =
                *(const float4*)(B + (size_t)(k0 + row) * N + bn + c4 * 4);
        }
        __syncthreads();

#pragma unroll
        for (int ks = 0; ks < 4; ks++) {
            int k = ks * 8;
            unsigned aHi[2][4], aLo[2][4];
#pragma unroll
            for (int mt = 0; mt < 2; mt++) {
                int r0 = wm * 32 + mt * 16 + lq;
                float f0 = As[r0    ][k + lr];
                float f1 = As[r0 + 8][k + lr];
                float f2 = As[r0    ][k + 4 + lr];
                float f3 = As[r0 + 8][k + 4 + lr];
                split_tf32(f0, aHi[mt][0], aLo[mt][0]);
                split_tf32(f1, aHi[mt][1], aLo[mt][1]);
                split_tf32(f2, aHi[mt][2], aLo[mt][2]);
                split_tf32(f3, aHi[mt][3], aLo[mt][3]);
            }
            unsigned bHi[4][2], bLo[4][2];
#pragma unroll
            for (int nt = 0; nt < 4; nt++) {
                int c = wn * 32 + nt * 8 + lq;
                float f0 = Bs[k + lr    ][c];
                float f1 = Bs[k + 4 + lr][c];
                split_tf32(f0, bHi[nt][0], bLo[nt][0]);
                split_tf32(f1, bHi[nt][1], bLo[nt][1]);
            }
#pragma unroll
            for (int mt = 0; mt < 2; mt++)
#pragma unroll
                for (int nt = 0; nt < 4; nt++) {
                    mma_tf32(acc[mt][nt], aLo[mt], bHi[nt]);
                    mma_tf32(acc[mt][nt], aHi[mt], bLo[nt]);
                    mma_tf32(acc[mt][nt], aHi[mt], bHi[nt]);
                }
        }
        __syncthreads();
    }

#pragma unroll
    for (int mt = 0; mt < 2; mt++) {
#pragma unroll
        for (int nt = 0; nt < 4; nt++) {
            int gr0 = bm + wm * 32 + mt * 16 + lq;
            int gc  = bn + wn * 32 + nt * 8 + lr * 2;
            if (gr0 < M)
                *(float2*)(g_bufA + (size_t)gr0 * N + gc) =
                    make_float2(acc[mt][nt][0], acc[mt][nt][1]);
            if (gr0 + 8 < M)
                *(float2*)(g_bufA + (size_t)(gr0 + 8) * N + gc) =
                    make_float2(acc[mt][nt][2], acc[mt][nt][3]);
        }
    }
}

// ---------------- fused GCN aggregation, feature-sliced --------------------
// grid (N_NODES, 2): blockIdx.y selects 128-feature slice -> 51MB L2-resident
// working set per pass. 64 threads/block, float2 per thread, no atomics.
__global__ __launch_bounds__(64)
void k_gcn(const float* __restrict__ bias) {
    int d   = blockIdx.x;
    int fo  = blockIdx.y * 64 + threadIdx.x;   // float2 index within 128-float2 row
    int beg = g_row_ptr[d], end = g_row_ptr[d + 1];
    const float2* xw2 = (const float2*)g_bufA;
    float2 acc = make_float2(0.f, 0.f);
    int j = beg;
    for (; j + 3 < end; j += 4) {
        int s0 = g_csr_src[j],     s1 = g_csr_src[j + 1];
        int s2 = g_csr_src[j + 2], s3 = g_csr_src[j + 3];
        float c0 = g_csr_coef[j],     c1 = g_csr_coef[j + 1];
        float c2 = g_csr_coef[j + 2], c3 = g_csr_coef[j + 3];
        float2 v0 = xw2[(size_t)s0 * 128 + fo];
        float2 v1 = xw2[(size_t)s1 * 128 + fo];
        float2 v2 = xw2[(size_t)s2 * 128 + fo];
        float2 v3 = xw2[(size_t)s3 * 128 + fo];
        acc.x += c0 * v0.x + c1 * v1.x + c2 * v2.x + c3 * v3.x;
        acc.y += c0 * v0.y + c1 * v1.y + c2 * v2.y + c3 * v3.y;
    }
    for (; j < end; j++) {
        int s = g_csr_src[j];
        float c = g_csr_coef[j];
        float2 v = xw2[(size_t)s * 128 + fo];
        acc.x += c * v.x;
        acc.y += c * v.y;
    }
    float dis = g_dis[d];
    float d2 = dis * dis;
    float2 sv = xw2[(size_t)d * 128 + fo];
    acc.x += d2 * sv.x + bias[fo * 2];
    acc.y += d2 * sv.y + bias[fo * 2 + 1];
    acc.x = fmaxf(acc.x, 0.f);
    acc.y = fmaxf(acc.y, 0.f);
    ((float2*)g_bufB)[(size_t)d * 128 + fo] = acc;
}

// ---------------- segment mean pool (two-phase) ----------------------------
__global__ void k_pool1() {
    int t = blockIdx.x >> 4;
    int p = blockIdx.x & 15;
    int f = threadIdx.x;
    int r0 = p * 98;
    int r1 = r0 + 98; if (r1 > CHUNK) r1 = CHUNK;
    const float* base = g_bufB + ((size_t)t * CHUNK + r0) * D;
    float acc = 0.f;
#pragma unroll 4
    for (int i = 0; i < r1 - r0; i++) acc += base[(size_t)i * D + f];
    g_ppart[t][p][f] = acc;
}

__global__ void k_pool2() {
    int t = blockIdx.x, f = threadIdx.x;
    float acc = 0.f;
#pragma unroll
    for (int p = 0; p < POOL_PARTS; p++) acc += g_ppart[t][p][f];
    g_pooled[t * D + f] = acc * (1.0f / (float)CHUNK);
}

// ---------------- gx = pooled @ w_ih^T + b_ih (parallel over t,j) ----------
__global__ void k_gx(const float* __restrict__ w_ih, const float* __restrict__ b_ih) {
    int idx = blockIdx.x * blockDim.x + threadIdx.x;
    if (idx >= T_STEPS * 3 * D) return;
    int t = idx / (3 * D), j = idx % (3 * D);
    const float4* w = (const float4*)(w_ih + (size_t)j * D);
    const float4* p = (const float4*)(g_pooled + t * D);
    float acc = b_ih[j];
#pragma unroll 4
    for (int k = 0; k < D / 4; k++) {
        float4 a = w[k], b = p[k];
        acc += a.x * b.x + a.y * b.y + a.z * b.z + a.w * b.w;
    }
    g_gx[idx] = acc;
}

// ---------------- distributed GRU: 32 blocks, smem-resident weights --------
__global__ void k_gru_reset() {
    int i = blockIdx.x * blockDim.x + threadIdx.x;
    if (i < (T_STEPS + 2) * GRU_NB) ((volatile int*)g_gru_flag)[i] = 0;
}

__device__ __forceinline__ void gru_barrier(int id, int b, int tid) {
    __syncthreads();
    if (tid == 0) {
        __threadfence();
        g_gru_flag[id][b] = 1;
    }
    if (tid < GRU_NB) {
        while (g_gru_flag[id][tid] == 0) { }
    }
    __syncthreads();
}

__global__ __launch_bounds__(256)
void k_gru(const float* __restrict__ w_hh, const float* __restrict__ b_hh,
           const float* __restrict__ Wc, const float* __restrict__ bc,
           float* __restrict__ out) {
    __shared__ float w_sh[3 * GRU_UPB][D];   // 24 rows x 256 = 24KB
    __shared__ float h_sh[D];
    __shared__ float gh_sh[3 * GRU_UPB];
    __shared__ float bhh_sh[3 * GRU_UPB];
    int b = blockIdx.x, tid = threadIdx.x;
    int warp = tid >> 5, lane = tid & 31;

    // row l (0..23): gate g = l/8, unit u = b*8 + l%8, global row = g*256 + u
    for (int idx = tid; idx < 3 * GRU_UPB * D; idx += 256) {
        int l = idx >> 8, k = idx & 255;
        int row = (l >> 3) * D + b * GRU_UPB + (l & 7);
        w_sh[l][k] = w_hh[(size_t)row * D + k];
    }
    if (tid < 3 * GRU_UPB) {
        int row = (tid >> 3) * D + b * GRU_UPB + (tid & 7);
        bhh_sh[tid] = b_hh[row];
    }
    if (tid < GRU_UPB) g_h[b * GRU_UPB + tid] = 0.f;
    __threadfence();
    gru_barrier(0, b, tid);

    for (int t = 0; t < T_STEPS; t++) {
        h_sh[tid] = g_h[tid];
        __syncthreads();
#pragma unroll
        for (int rr = 0; rr < 3; rr++) {
            int l = warp * 3 + rr;
            const float4* w = (const float4*)&w_sh[l][lane * 8];
            float4 a0 = w[0], a1 = w[1];
            float4 h0 = *(const float4*)&h_sh[lane * 8];
            float4 h1 = *(const float4*)&h_sh[lane * 8 + 4];
            float p = a0.x * h0.x + a0.y * h0.y + a0.z * h0.z + a0.w * h0.w
                    + a1.x * h1.x + a1.y * h1.y + a1.z * h1.z + a1.w * h1.w;
#pragma unroll
            for (int o = 16; o > 0; o >>= 1) p += __shfl_down_sync(0xffffffffu, p, o);
            if (lane == 0) gh_sh[l] = p + bhh_sh[l];
        }
        __syncthreads();
        if (tid < GRU_UPB) {
            int u = b * GRU_UPB + tid;
            float xr = g_gx[t * 3 * D + u];
            float xz = g_gx[t * 3 * D + D + u];
            float xn = g_gx[t * 3 * D + 2 * D + u];
            float r_ = 1.f / (1.f + expf(-(xr + gh_sh[tid])));
            float z_ = 1.f / (1.f + expf(-(xz + gh_sh[GRU_UPB + tid])));
            float n_ = tanhf(xn + r_ * gh_sh[2 * GRU_UPB + tid]);
            g_h[u] = (1.f - z_) * n_ + z_ * h_sh[u];
        }
        __threadfence();
        gru_barrier(t + 1, b, tid);
    }
    if (b == 0 && tid < D_OUT) {
        float acc = bc[tid];
        for (int k = 0; k < D; k++) acc += Wc[(size_t)tid * D + k] * g_h[k];
        out[tid] = acc;
    }
}

// ---------------- launch ----------------------------------------------------
extern "C" void kernel_launch(void* const* d_in, const int* in_sizes, int n_in,
                              void* d_out, int out_size) {
    // 0:x 1:edge_index 2:ptr 3:W1 4:b1 5:W2 6:b2 7:w_ih 8:w_hh 9:b_ih 10:b_hh 11:Wc 12:bc
    int idx_x = 0, idx_ei = 1;
    if (in_sizes[idx_ei] != 2 * N_EDGES) {
        for (int i = 0; i < n_in; i++) if (in_sizes[i] == 2 * N_EDGES) { idx_ei = i; break; }
    }
    if (in_sizes[idx_x] != N_NODES * D) {
        for (int i = 0; i < n_in; i++) if (in_sizes[i] == N_NODES * D) { idx_x = i; break; }
    }

    const float* x    = (const float*)d_in[idx_x];
    const int*   ei   = (const int*)d_in[idx_ei];
    const float* W1   = (const float*)d_in[3];
    const float* b1   = (const float*)d_in[4];
    const float* W2   = (const float*)d_in[5];
    const float* b2   = (const float*)d_in[6];
    const float* w_ih = (const float*)d_in[7];
    const float* w_hh = (const float*)d_in[8];
    const float* b_ih = (const float*)d_in[9];
    const float* b_hh = (const float*)d_in[10];
    const float* Wc   = (const float*)d_in[11];
    const float* bc   = (const float*)d_in[12];
    float* out = (float*)d_out;

    const int* src = ei;
    const int* dst = ei + N_EDGES;

    // CSR by dst (counting sort), deg_inv_sqrt
    k_zero_cnt<<<(N_NODES + 255) / 256, 256>>>();
    k_hist<<<(N_EDGES + 255) / 256, 256>>>(dst);
    k_scan1<<<NB_SCAN, 256>>>();
    k_scan2<<<1, 128>>>(NB_SCAN);
    k_scan3<<<(N_NODES + 255) / 256, 256>>>();
    k_scatter<<<(N_EDGES + 255) / 256, 256>>>(src, dst);

    dim3 gemmGrid(4, (N_NODES + 127) / 128);
    dim3 gcnGrid(N_NODES, 2);

    // layer 1
    k_gemm_tc<<<gemmGrid, 256>>>(x, W1, N_NODES);
    k_gcn<<<gcnGrid, 64>>>(b1);

    // layer 2
    k_gemm_tc<<<gemmGrid, 256>>>(nullptr, W2, N_NODES);
    k_gcn<<<gcnGrid, 64>>>(b2);

    // pool -> gx -> GRU(+classifier)
    k_pool1<<<T_STEPS * POOL_PARTS, 256>>>();
    k_pool2<<<T_STEPS, 256>>>();
    k_gx<<<(T_STEPS * 3 * D + 127) / 128, 128>>>(w_ih, b_ih);
    k_gru_reset<<<((T_STEPS + 2) * GRU_NB + 255) / 256, 256>>>();
    k_gru<<<GRU_NB, 256>>>(w_hh, b_hh, Wc, bc, out);
}